// round 3
// baseline (speedup 1.0000x reference)
#include <cuda_runtime.h>

// Unfold (im2col) for x:(B=16, C=128, H=64, W=64), k=3, pad=1.
// out[b, c*9 + p, h*W + w] = x[b, c, h+dh-1, w+dw-1] (zero-padded), p = dh*3+dw.
// DRAM-write bound: 302 MB write + ~34 MB read. Target ~48 us.
//
// R3 version: 8 outputs per thread, vectorized (float4) halo loads,
// streaming (.cs) stores to keep input resident in L2.

#define B_ 16
#define C_ 128
#define H_ 64
#define W_ 64
#define PLANE (H_ * W_)   // 4096

__global__ __launch_bounds__(256) void unfold_kernel(
    const float* __restrict__ x, float* __restrict__ out)
{
    int idx = blockIdx.x * blockDim.x + threadIdx.x;
    // Each thread handles 8 consecutive w of one (b, c, h) row.
    // idx layout: [bc (11b)] [h (6b)] [wg (3b)]
    int wg = idx & 7;            // w-group 0..7
    int h  = (idx >> 3) & 63;    // 0..63
    int bc = idx >> 9;           // b*C + c, 0..2047
    int w0 = wg << 3;            // 0,8,...,56

    const float* plane = x + (size_t)bc * PLANE;

    // Halo window: rows h-1..h+1, cols w0-1..w0+8 (10 values per row).
    // Per row: 1 scalar + 2x float4 + 1 scalar (all in-bounds float4s).
    float v[3][10];
#pragma unroll
    for (int r = 0; r < 3; r++) {
        int hh = h + r - 1;
        if (hh >= 0 && hh < H_) {
            const float* row = plane + hh * W_;
            v[r][0] = (w0 > 0) ? row[w0 - 1] : 0.0f;
            float4 a = *reinterpret_cast<const float4*>(row + w0);
            float4 b = *reinterpret_cast<const float4*>(row + w0 + 4);
            v[r][1] = a.x; v[r][2] = a.y; v[r][3] = a.z; v[r][4] = a.w;
            v[r][5] = b.x; v[r][6] = b.y; v[r][7] = b.z; v[r][8] = b.w;
            v[r][9] = (w0 < W_ - 8) ? row[w0 + 8] : 0.0f;
        } else {
#pragma unroll
            for (int c = 0; c < 10; c++) v[r][c] = 0.0f;
        }
    }

    // 18 coalesced STG.128 streaming stores (2 per kernel position).
    float* outp = out + (size_t)bc * 9 * PLANE + h * W_ + w0;
#pragma unroll
    for (int p = 0; p < 9; p++) {
        int r  = p / 3;
        int cc = p % 3;
        float4 o0 = make_float4(v[r][cc],     v[r][cc + 1], v[r][cc + 2], v[r][cc + 3]);
        float4 o1 = make_float4(v[r][cc + 4], v[r][cc + 5], v[r][cc + 6], v[r][cc + 7]);
        __stcs(reinterpret_cast<float4*>(outp + (size_t)p * PLANE),     o0);
        __stcs(reinterpret_cast<float4*>(outp + (size_t)p * PLANE + 4), o1);
    }
}

extern "C" void kernel_launch(void* const* d_in, const int* in_sizes, int n_in,
                              void* d_out, int out_size)
{
    const float* x = (const float*)d_in[0];
    // d_in[1] is the identity "weights" buffer — unused (eye(9) by construction).
    float* out = (float*)d_out;

    const int total  = B_ * C_ * H_ * (W_ / 8);  // 1,048,576 threads
    const int tpb    = 256;
    const int blocks = total / tpb;              // 4096
    unfold_kernel<<<blocks, tpb>>>(x, out);
}

// round 4
// speedup vs baseline: 1.4203x; 1.4203x over previous
#include <cuda_runtime.h>

// Unfold (im2col) for x:(B=16, C=128, H=64, W=64), k=3, pad=1.
// out[b, c*9 + p, h*W + w] = x[b, c, h+dh-1, w+dw-1] (zero-padded), p = dh*3+dw.
// DRAM-write bound: 302 MB write + ~34 MB read.
//
// R3: R1 structure (4 outputs/thread, 2M threads, plain STG.128) with ONE
// change: vectorized halo loads (LDG.32 + LDG.128 + LDG.32 per row) instead
// of 18 predicated scalar loads.

#define B_ 16
#define C_ 128
#define H_ 64
#define W_ 64
#define PLANE (H_ * W_)   // 4096

__global__ __launch_bounds__(256) void unfold_kernel(
    const float* __restrict__ x, float* __restrict__ out)
{
    int idx = blockIdx.x * blockDim.x + threadIdx.x;
    // Each thread handles 4 consecutive w of one (b, c, h) row.
    // idx layout: [bc (11b)] [h (6b)] [wg (4b)]
    int wg = idx & 15;           // w-group 0..15
    int h  = (idx >> 4) & 63;    // 0..63
    int bc = idx >> 10;          // b*C + c, 0..2047
    int w0 = wg << 2;            // 0,4,...,60

    const float* plane = x + (size_t)bc * PLANE;

    // Halo window: rows h-1..h+1, cols w0-1..w0+4 (6 values per row).
    // Per row: scalar edge + aligned float4 + scalar edge = 3 loads.
    float v[3][6];
#pragma unroll
    for (int r = 0; r < 3; r++) {
        int hh = h + r - 1;
        if (hh >= 0 && hh < H_) {
            const float* row = plane + hh * W_;
            v[r][0] = (w0 > 0) ? row[w0 - 1] : 0.0f;
            float4 a = *reinterpret_cast<const float4*>(row + w0);
            v[r][1] = a.x; v[r][2] = a.y; v[r][3] = a.z; v[r][4] = a.w;
            v[r][5] = (w0 < W_ - 4) ? row[w0 + 4] : 0.0f;
        } else {
#pragma unroll
            for (int c = 0; c < 6; c++) v[r][c] = 0.0f;
        }
    }

    // 9 coalesced float4 stores, one per kernel position.
    float* outp = out + (size_t)bc * 9 * PLANE + h * W_ + w0;
#pragma unroll
    for (int p = 0; p < 9; p++) {
        int r  = p / 3;
        int cc = p % 3;
        float4 o = make_float4(v[r][cc], v[r][cc + 1], v[r][cc + 2], v[r][cc + 3]);
        *reinterpret_cast<float4*>(outp + (size_t)p * PLANE) = o;
    }
}

extern "C" void kernel_launch(void* const* d_in, const int* in_sizes, int n_in,
                              void* d_out, int out_size)
{
    const float* x = (const float*)d_in[0];
    // d_in[1] is the identity "weights" buffer — unused (eye(9) by construction).
    float* out = (float*)d_out;

    const int total  = B_ * C_ * H_ * (W_ / 4);  // 2,097,152 threads
    const int tpb    = 256;
    const int blocks = total / tpb;              // 8192
    unfold_kernel<<<blocks, tpb>>>(x, out);
}

// round 5
// speedup vs baseline: 1.4236x; 1.0023x over previous
#include <cuda_runtime.h>

// Unfold (im2col) for x:(B=16, C=128, H=64, W=64), k=3, pad=1.
// out[b, c*9 + p, h*W + w] = x[b, c, h+dh-1, w+dw-1] (zero-padded), p = dh*3+dw.
// DRAM-write bound: 302 MB write + ~34 MB read.
//
// R4: interleave per-row. Load row r's halo (scalar + float4 + scalar),
// immediately store its 3 kernel positions. Cuts live registers ~2x and
// starts the store stream 2 rows earlier than the batched version.

#define B_ 16
#define C_ 128
#define H_ 64
#define W_ 64
#define PLANE (H_ * W_)   // 4096

__global__ __launch_bounds__(256) void unfold_kernel(
    const float* __restrict__ x, float* __restrict__ out)
{
    int idx = blockIdx.x * blockDim.x + threadIdx.x;
    // Each thread handles 4 consecutive w of one (b, c, h) row.
    // idx layout: [bc (11b)] [h (6b)] [wg (4b)]
    int wg = idx & 15;           // w-group 0..15
    int h  = (idx >> 4) & 63;    // 0..63
    int bc = idx >> 10;          // b*C + c, 0..2047
    int w0 = wg << 2;            // 0,4,...,60

    const float* plane = x + (size_t)bc * PLANE;
    float* outp = out + (size_t)bc * 9 * PLANE + h * W_ + w0;

#pragma unroll
    for (int r = 0; r < 3; r++) {
        int hh = h + r - 1;
        float v0, v1, v2, v3, v4, v5;
        if (hh >= 0 && hh < H_) {
            const float* row = plane + hh * W_;
            v0 = (w0 > 0) ? row[w0 - 1] : 0.0f;
            float4 a = *reinterpret_cast<const float4*>(row + w0);
            v1 = a.x; v2 = a.y; v3 = a.z; v4 = a.w;
            v5 = (w0 < W_ - 4) ? row[w0 + 4] : 0.0f;
        } else {
            v0 = v1 = v2 = v3 = v4 = v5 = 0.0f;
        }

        float* op = outp + (size_t)(r * 3) * PLANE;
        *reinterpret_cast<float4*>(op)              = make_float4(v0, v1, v2, v3);
        *reinterpret_cast<float4*>(op + PLANE)      = make_float4(v1, v2, v3, v4);
        *reinterpret_cast<float4*>(op + 2 * PLANE)  = make_float4(v2, v3, v4, v5);
    }
}

extern "C" void kernel_launch(void* const* d_in, const int* in_sizes, int n_in,
                              void* d_out, int out_size)
{
    const float* x = (const float*)d_in[0];
    // d_in[1] is the identity "weights" buffer — unused (eye(9) by construction).
    float* out = (float*)d_out;

    const int total  = B_ * C_ * H_ * (W_ / 4);  // 2,097,152 threads
    const int tpb    = 256;
    const int blocks = total / tpb;              // 8192
    unfold_kernel<<<blocks, tpb>>>(x, out);
}